// round 17
// baseline (speedup 1.0000x reference)
#include <cuda_runtime.h>
#include <cstdint>

// ---------------- problem constants ----------------
#define D_DIM 1024
#define ER    256
#define NL    3
#define BM    64
#define NTHR  256
#define NBLK  (32768 / BM)   // 512
#define KC    16

// smem strides (floats)
#define BSTR 264             // B chunk row stride (264%32==8 -> b-frag conflict-free)
#define CBSTR 68             // Cb block row stride (68%32==4 -> conflict-free)
#define VSTR 260             // vS row stride (cols 0..255 data, 256..259 = gates)
#define XSTR 20              // x chunk row stride
#define ESTR 264             // epilogue stage stride

// smem float offsets
// scratch (8704 fl): B stages [2][16][264]=8448 | Cb blocks [2][64][68]=8704 |
//                    gpart [8][64][8]=4096 | epi stage [32][264]=8448
#define OFF_SCR  0
#define OFF_VS   8704        // [64][260] = 16640 (gates in per-row padding)
#define OFF_XS   25344       // [2][64][20] = 2560
#define OFF_GWS  27904       // [2][16][8] = 256
#define SMEM_FL  28160
#define SMEM_BYTES (SMEM_FL * 4)   // 112640 B -> 2 CTAs/SM

#define BS_STG 4224          // 16*264
#define CB_STG 4352          // 64*68
#define XS_STG 1280          // 64*20
#define GW_STG 128           // 16*8

// ---------------- prepped weights ----------------
__device__ float g_Vt[NL * D_DIM * ER];    // [l][d][er]
__device__ float g_Ut[NL * ER * D_DIM];    // [l][er][d]
__device__ float g_Cb[NL * ER * ER];       // [l][k][n] block-diag
__device__ float g_gwT[D_DIM * 8];         // [d][e] (e>=4 zero)

// ---------------- helpers ----------------
__device__ __forceinline__ float rna_tf32(float x) {
    uint32_t u; asm("cvt.rna.tf32.f32 %0, %1;" : "=r"(u) : "f"(x));
    return __uint_as_float(u);
}
__device__ __forceinline__ uint32_t fu(float x) { return __float_as_uint(x); }

__device__ __forceinline__ void mma_tf32(float* d,
                                         uint32_t a0, uint32_t a1, uint32_t a2, uint32_t a3,
                                         uint32_t b0, uint32_t b1) {
    asm volatile(
        "mma.sync.aligned.m16n8k8.row.col.f32.tf32.tf32.f32 "
        "{%0,%1,%2,%3}, {%4,%5,%6,%7}, {%8,%9}, {%0,%1,%2,%3};\n"
        : "+f"(d[0]), "+f"(d[1]), "+f"(d[2]), "+f"(d[3])
        : "r"(a0), "r"(a1), "r"(a2), "r"(a3), "r"(b0), "r"(b1));
}

__device__ __forceinline__ void cp16(uint32_t saddr, const float* g) {
    asm volatile("cp.async.cg.shared.global [%0], [%1], 16;\n" :: "r"(saddr), "l"(g));
}
#define CP_COMMIT() asm volatile("cp.async.commit_group;\n" ::: "memory")
#define CP_WAIT0()  asm volatile("cp.async.wait_group 0;\n" ::: "memory")

// ---------------- weight prep (index math verified in passing runs) ----------------
__global__ void prep_k(const float* __restrict__ U, const float* __restrict__ V,
                       const float* __restrict__ C, const float* __restrict__ gw) {
    const int stride = gridDim.x * blockDim.x;
    const int t0 = blockIdx.x * blockDim.x + threadIdx.x;

    for (int i = t0; i < NL * D_DIM * ER; i += stride) {
        const int l = i / (D_DIM * ER);
        const int rem = i % (D_DIM * ER);
        {   // Vt[l][d][e*64+r] = V[l,e,d,r]
            const int d = rem >> 8, n = rem & 255, e = n >> 6, r = n & 63;
            g_Vt[i] = rna_tf32(V[(((l * 4 + e) * D_DIM + d) * 64) + r]);
        }
        {   // Ut[l][e*64+r][d] = U[l,e,d,r]
            const int er = rem >> 10, d = rem & 1023, e = er >> 6, r = er & 63;
            g_Ut[i] = rna_tf32(U[(((l * 4 + e) * D_DIM + d) * 64) + r]);
        }
    }
    for (int i = t0; i < NL * ER * ER; i += stride) {
        const int l = i / (ER * ER);
        const int rem = i % (ER * ER);
        const int sg = rem >> 8, rg = rem & 255;     // k = sg, n = rg
        const int es = sg >> 6, er_ = rg >> 6;
        g_Cb[i] = (es == er_)
            ? rna_tf32(C[(((l * 4 + es) * 64 + (rg & 63)) * 64) + (sg & 63)])
            : 0.0f;
    }
    for (int i = t0; i < D_DIM * 8; i += stride) {
        const int d = i >> 3, e = i & 7;
        g_gwT[i] = (e < 4) ? rna_tf32(gw[e * D_DIM + d]) : 0.0f;
    }
}

// ---------------- fused layer kernel ----------------
__global__ void __launch_bounds__(NTHR, 2)
layer_k(const float* __restrict__ xin, float* __restrict__ xout,
        const float* __restrict__ x0g, const float* __restrict__ bias_all,
        int l, int x0_is_xin) {
    extern __shared__ float sm[];
    float* scr = sm + OFF_SCR;
    float* vS  = sm + OFF_VS;
    float* xs  = sm + OFF_XS;
    float* gws = sm + OFF_GWS;
    uint32_t sbase = (uint32_t)__cvta_generic_to_shared(sm);

    const int tid = threadIdx.x;
    const int warp = tid >> 5, lane = tid & 31;
    const int g = lane >> 2, t = lane & 3;
    const int mw = warp >> 2;          // m-half: rows mw*32..+31
    const int nw = warp & 3;           // n-slice: cols nw*64..+63 (== expert nw)
    const int brow = blockIdx.x * BM;

    const float* Vt = g_Vt + (size_t)l * (D_DIM * ER);
    const float* Ut = g_Ut + (size_t)l * (ER * D_DIM);
    const float* Cb = g_Cb + (size_t)l * (ER * ER);
    const float* bl = bias_all + l * D_DIM;

    float acc[64];                     // [mtl(2)][nt(8)][4]
    float gacc[16];                    // [mt(4)][4]
    #pragma unroll
    for (int i = 0; i < 64; i++) acc[i] = 0.0f;
    #pragma unroll
    for (int i = 0; i < 16; i++) gacc[i] = 0.0f;

    // ---- loaders ----
    auto load_B = [&](int s, const float* src, int row0, int srcstride, int coloff) {
        #pragma unroll
        for (int j = 0; j < 4; j++) {
            int u = tid + j * 256;
            int r = u >> 6, c4 = u & 63;
            cp16(sbase + (uint32_t)((OFF_SCR + s * BS_STG + r * BSTR + c4 * 4) * 4),
                 src + (size_t)(row0 + r) * srcstride + coloff + c4 * 4);
        }
    };
    auto load_x = [&](int s, int k0) {
        int r = tid >> 2, c4 = tid & 3;
        cp16(sbase + (uint32_t)((OFF_XS + s * XS_STG + r * XSTR + c4 * 4) * 4),
             xin + (size_t)(brow + r) * D_DIM + k0 + c4 * 4);
    };
    auto load_g = [&](int s, int k0) {
        if (tid < 32) {
            int r = tid >> 1, c4 = tid & 1;
            cp16(sbase + (uint32_t)((OFF_GWS + s * GW_STG + r * 8 + c4 * 4) * 4),
                 g_gwT + (k0 + r) * 8 + c4 * 4);
        }
    };

    // ============ Phase A: v1_pre = x @ Vt (M=64,N=256,K=1024) + gating ============
    load_B(0, Vt, 0, ER, 0); load_x(0, 0); load_g(0, 0); CP_COMMIT();

    for (int c = 0; c < 64; c++) {
        CP_WAIT0();
        __syncthreads();
        const int s = c & 1;
        if (c + 1 < 64) {
            load_B(s ^ 1, Vt, (c + 1) * KC, ER, 0);
            load_x(s ^ 1, (c + 1) * KC);
            load_g(s ^ 1, (c + 1) * KC);
            CP_COMMIT();
        }
        const float* xb = xs + s * XS_STG;
        const float* bb = scr + s * BS_STG;
        const float* gb = gws + s * GW_STG;
        const bool dogate = ((c & 7) == warp);
        #pragma unroll
        for (int kk = 0; kk < 2; kk++) {
            const int kb = kk * 8;
            const int rb = mw * 32;
            uint32_t a0 = fu(xb[(rb + g) * XSTR + kb + t]);
            uint32_t a1 = fu(xb[(rb + g + 8) * XSTR + kb + t]);
            uint32_t a2 = fu(xb[(rb + g) * XSTR + kb + t + 4]);
            uint32_t a3 = fu(xb[(rb + g + 8) * XSTR + kb + t + 4]);
            uint32_t a4 = fu(xb[(rb + 16 + g) * XSTR + kb + t]);
            uint32_t a5 = fu(xb[(rb + 24 + g) * XSTR + kb + t]);
            uint32_t a6 = fu(xb[(rb + 16 + g) * XSTR + kb + t + 4]);
            uint32_t a7 = fu(xb[(rb + 24 + g) * XSTR + kb + t + 4]);
            #pragma unroll
            for (int nt = 0; nt < 8; nt++) {
                const int col = nw * 64 + nt * 8 + g;
                uint32_t b0 = fu(bb[(kb + t) * BSTR + col]);
                uint32_t b1 = fu(bb[(kb + t + 4) * BSTR + col]);
                mma_tf32(acc + nt * 4,      a0, a1, a2, a3, b0, b1);
                mma_tf32(acc + 32 + nt * 4, a4, a5, a6, a7, b0, b1);
            }
            if (dogate) {
                const int ro = (1 - mw) * 32;
                uint32_t o0 = fu(xb[(ro + g) * XSTR + kb + t]);
                uint32_t o1 = fu(xb[(ro + g + 8) * XSTR + kb + t]);
                uint32_t o2 = fu(xb[(ro + g) * XSTR + kb + t + 4]);
                uint32_t o3 = fu(xb[(ro + g + 8) * XSTR + kb + t + 4]);
                uint32_t o4 = fu(xb[(ro + 16 + g) * XSTR + kb + t]);
                uint32_t o5 = fu(xb[(ro + 24 + g) * XSTR + kb + t]);
                uint32_t o6 = fu(xb[(ro + 16 + g) * XSTR + kb + t + 4]);
                uint32_t o7 = fu(xb[(ro + 24 + g) * XSTR + kb + t + 4]);
                uint32_t gb0 = fu(gb[(kb + t) * 8 + g]);
                uint32_t gb1 = fu(gb[(kb + t + 4) * 8 + g]);
                mma_tf32(gacc + (mw * 2) * 4,       a0, a1, a2, a3, gb0, gb1);
                mma_tf32(gacc + (mw * 2 + 1) * 4,   a4, a5, a6, a7, gb0, gb1);
                mma_tf32(gacc + ((1 - mw) * 2) * 4,     o0, o1, o2, o3, gb0, gb1);
                mma_tf32(gacc + ((1 - mw) * 2 + 1) * 4, o4, o5, o6, o7, gb0, gb1);
            }
        }
    }
    __syncthreads();   // scratch free (gpart aliases it)

    // v1 = rna(tanh(acc)) -> vS ; gating partials -> gpart
    float* gpart = scr;
    #pragma unroll
    for (int mtl = 0; mtl < 2; mtl++) {
        const int r0 = mw * 32 + mtl * 16 + g;
        #pragma unroll
        for (int nt = 0; nt < 8; nt++) {
            const int col = nw * 64 + nt * 8 + 2 * t;
            vS[r0 * VSTR + col]           = rna_tf32(tanhf(acc[mtl * 32 + nt * 4 + 0]));
            vS[r0 * VSTR + col + 1]       = rna_tf32(tanhf(acc[mtl * 32 + nt * 4 + 1]));
            vS[(r0 + 8) * VSTR + col]     = rna_tf32(tanhf(acc[mtl * 32 + nt * 4 + 2]));
            vS[(r0 + 8) * VSTR + col + 1] = rna_tf32(tanhf(acc[mtl * 32 + nt * 4 + 3]));
        }
    }
    #pragma unroll
    for (int mt = 0; mt < 4; mt++) {
        const int row = mt * 16 + g;
        const int cc = 2 * t;
        gpart[warp * 512 + row * 8 + cc]           = gacc[mt * 4 + 0];
        gpart[warp * 512 + row * 8 + cc + 1]       = gacc[mt * 4 + 1];
        gpart[warp * 512 + (row + 8) * 8 + cc]     = gacc[mt * 4 + 2];
        gpart[warp * 512 + (row + 8) * 8 + cc + 1] = gacc[mt * 4 + 3];
    }
    __syncthreads();

    // softmax over experts: 64 rows x 4 experts = 256 threads
    {
        const int row = tid >> 2, e = tid & 3;
        float s = 0.0f;
        #pragma unroll
        for (int w = 0; w < 8; w++) s += gpart[w * 512 + row * 8 + e];
        float m = s;
        m = fmaxf(m, __shfl_xor_sync(0xffffffffu, m, 1));
        m = fmaxf(m, __shfl_xor_sync(0xffffffffu, m, 2));
        float p = __expf(s - m);
        float su = p;
        su += __shfl_xor_sync(0xffffffffu, su, 1);
        su += __shfl_xor_sync(0xffffffffu, su, 2);
        vS[row * VSTR + 256 + e] = p / su;   // gates live in vS row padding
    }
    __syncthreads();

    // ============ Phase B: v2_pre = v1 @ Cb, block-diagonal (K=64 per expert) ============
    #pragma unroll
    for (int i = 0; i < 64; i++) acc[i] = 0.0f;

    // round r covers experts {2r, 2r+1}; block b at scr + b*CB_STG, stride 68
    auto load_cb = [&](int r) {
        #pragma unroll
        for (int j = 0; j < 8; j++) {
            int u = tid + j * 256;          // 2048 units = 2 blocks x 64 rows x 16 units
            int b = u >> 10, v = u & 1023;
            int row = v >> 4, c4 = v & 15;
            int e = 2 * r + b;
            cp16(sbase + (uint32_t)((OFF_SCR + b * CB_STG + row * CBSTR + c4 * 4) * 4),
                 Cb + (size_t)(e * 64 + row) * ER + e * 64 + c4 * 4);
        }
    };
    load_cb(0); CP_COMMIT();
    for (int r = 0; r < 2; r++) {
        CP_WAIT0();
        __syncthreads();
        if ((nw >> 1) == r) {
            const float* blk = scr + (nw & 1) * CB_STG;
            #pragma unroll
            for (int ks = 0; ks < 8; ks++) {
                const int kb = ks * 8;
                const int kg = nw * 64 + kb;      // A col range = expert block
                const int rb = mw * 32;
                uint32_t a0 = fu(vS[(rb + g) * VSTR + kg + t]);
                uint32_t a1 = fu(vS[(rb + g + 8) * VSTR + kg + t]);
                uint32_t a2 = fu(vS[(rb + g) * VSTR + kg + t + 4]);
                uint32_t a3 = fu(vS[(rb + g + 8) * VSTR + kg + t + 4]);
                uint32_t a4 = fu(vS[(rb + 16 + g) * VSTR + kg + t]);
                uint32_t a5 = fu(vS[(rb + 24 + g) * VSTR + kg + t]);
                uint32_t a6 = fu(vS[(rb + 16 + g) * VSTR + kg + t + 4]);
                uint32_t a7 = fu(vS[(rb + 24 + g) * VSTR + kg + t + 4]);
                #pragma unroll
                for (int nt = 0; nt < 8; nt++) {
                    const int lc = nt * 8 + g;
                    uint32_t b0 = fu(blk[(kb + t) * CBSTR + lc]);
                    uint32_t b1 = fu(blk[(kb + t + 4) * CBSTR + lc]);
                    mma_tf32(acc + nt * 4,      a0, a1, a2, a3, b0, b1);
                    mma_tf32(acc + 32 + nt * 4, a4, a5, a6, a7, b0, b1);
                }
            }
        }
        __syncthreads();                   // compute done before block reload
        if (r == 0) { load_cb(1); CP_COMMIT(); }
    }

    // w = rna(gate * tanh(v2_pre)) -> vS (expert of this warp's cols = nw)
    #pragma unroll
    for (int mtl = 0; mtl < 2; mtl++) {
        const int r0 = mw * 32 + mtl * 16 + g;
        const float g0 = vS[r0 * VSTR + 256 + nw];
        const float g1 = vS[(r0 + 8) * VSTR + 256 + nw];
        #pragma unroll
        for (int nt = 0; nt < 8; nt++) {
            const int col = nw * 64 + nt * 8 + 2 * t;
            vS[r0 * VSTR + col]           = rna_tf32(g0 * tanhf(acc[mtl * 32 + nt * 4 + 0]));
            vS[r0 * VSTR + col + 1]       = rna_tf32(g0 * tanhf(acc[mtl * 32 + nt * 4 + 1]));
            vS[(r0 + 8) * VSTR + col]     = rna_tf32(g1 * tanhf(acc[mtl * 32 + nt * 4 + 2]));
            vS[(r0 + 8) * VSTR + col + 1] = rna_tf32(g1 * tanhf(acc[mtl * 32 + nt * 4 + 3]));
        }
    }
    __syncthreads();

    // ============ Phase C: out = w @ Ut (M=64, N=1024 in 4 passes, K=256) ============
    for (int p = 0; p < 4; p++) {
        #pragma unroll
        for (int i = 0; i < 64; i++) acc[i] = 0.0f;
        load_B(0, Ut, 0, D_DIM, p * 256); CP_COMMIT();
        for (int c = 0; c < 16; c++) {
            CP_WAIT0();
            __syncthreads();
            const int s = c & 1;
            if (c + 1 < 16) { load_B(s ^ 1, Ut, (c + 1) * KC, D_DIM, p * 256); CP_COMMIT(); }
            const float* bb = scr + s * BS_STG;
            #pragma unroll
            for (int kk = 0; kk < 2; kk++) {
                const int kg = c * KC + kk * 8;
                const int kb = kk * 8;
                const int rb = mw * 32;
                uint32_t a0 = fu(vS[(rb + g) * VSTR + kg + t]);
                uint32_t a1 = fu(vS[(rb + g + 8) * VSTR + kg + t]);
                uint32_t a2 = fu(vS[(rb + g) * VSTR + kg + t + 4]);
                uint32_t a3 = fu(vS[(rb + g + 8) * VSTR + kg + t + 4]);
                uint32_t a4 = fu(vS[(rb + 16 + g) * VSTR + kg + t]);
                uint32_t a5 = fu(vS[(rb + 24 + g) * VSTR + kg + t]);
                uint32_t a6 = fu(vS[(rb + 16 + g) * VSTR + kg + t + 4]);
                uint32_t a7 = fu(vS[(rb + 24 + g) * VSTR + kg + t + 4]);
                #pragma unroll
                for (int nt = 0; nt < 8; nt++) {
                    const int col = nw * 64 + nt * 8 + g;
                    uint32_t b0 = fu(bb[(kb + t) * BSTR + col]);
                    uint32_t b1 = fu(bb[(kb + t + 4) * BSTR + col]);
                    mma_tf32(acc + nt * 4,      a0, a1, a2, a3, b0, b1);
                    mma_tf32(acc + 32 + nt * 4, a4, a5, a6, a7, b0, b1);
                }
            }
        }
        __syncthreads();   // scratch free -> epilogue staging

        // epilogue: two 32-row halves staged in scr[32][264]
        float* stg = scr;
        for (int h = 0; h < 2; h++) {
            if (mw == h) {
                #pragma unroll
                for (int mtl = 0; mtl < 2; mtl++) {
                    const int lr = mtl * 16 + g;
                    #pragma unroll
                    for (int nt = 0; nt < 8; nt++) {
                        const int col = nw * 64 + nt * 8 + 2 * t;
                        stg[lr * ESTR + col]           = acc[mtl * 32 + nt * 4 + 0];
                        stg[lr * ESTR + col + 1]       = acc[mtl * 32 + nt * 4 + 1];
                        stg[(lr + 8) * ESTR + col]     = acc[mtl * 32 + nt * 4 + 2];
                        stg[(lr + 8) * ESTR + col + 1] = acc[mtl * 32 + nt * 4 + 3];
                    }
                }
            }
            __syncthreads();
            #pragma unroll
            for (int it = 0; it < 8; it++) {
                const int i2 = tid + it * 256;
                const int rr = i2 >> 6, c4 = i2 & 63;
                const int gr = brow + h * 32 + rr;
                const int gc = p * 256 + c4 * 4;
                float4 s4 = *reinterpret_cast<const float4*>(stg + rr * ESTR + c4 * 4);
                float4 xv = *reinterpret_cast<const float4*>(xin + (size_t)gr * D_DIM + gc);
                float4 x0v = x0_is_xin ? xv
                           : *reinterpret_cast<const float4*>(x0g + (size_t)gr * D_DIM + gc);
                float4 bv = *reinterpret_cast<const float4*>(bl + gc);
                float4 o;
                o.x = xv.x + x0v.x * (s4.x + bv.x);
                o.y = xv.y + x0v.y * (s4.y + bv.y);
                o.z = xv.z + x0v.z * (s4.z + bv.z);
                o.w = xv.w + x0v.w * (s4.w + bv.w);
                *reinterpret_cast<float4*>(xout + (size_t)gr * D_DIM + gc) = o;
            }
            __syncthreads();
        }
    }
}

// ---------------- launch ----------------
extern "C" void kernel_launch(void* const* d_in, const int* in_sizes, int n_in,
                              void* d_out, int out_size) {
    const float* inputs = (const float*)d_in[0];
    const float* U      = (const float*)d_in[1];
    const float* V      = (const float*)d_in[2];
    const float* C      = (const float*)d_in[3];
    const float* gw     = (const float*)d_in[4];
    const float* bias   = (const float*)d_in[5];
    float* out = (float*)d_out;
    (void)in_sizes; (void)n_in; (void)out_size;

    cudaFuncSetAttribute(layer_k, cudaFuncAttributeMaxDynamicSharedMemorySize, SMEM_BYTES);

    prep_k<<<512, 256>>>(U, V, C, gw);
    layer_k<<<NBLK, NTHR, SMEM_BYTES>>>(inputs, out, inputs, bias, 0, 1);
    layer_k<<<NBLK, NTHR, SMEM_BYTES>>>(out,    out, inputs, bias, 1, 0);
    layer_k<<<NBLK, NTHR, SMEM_BYTES>>>(out,    out, inputs, bias, 2, 0);
}